// round 15
// baseline (speedup 1.0000x reference)
#include <cuda_runtime.h>
#include <cstdint>

#define BM 128
#define BN 128
#define BK 16
#define NTHREADS 128
#define STAGES 3

// ---------------- scratch (device globals; no allocations allowed) ----------
__device__ float g_x[33554432];
__device__ float g_z[33554432];
__device__ float g_q[33554432];
__device__ float g_k[33554432];
__device__ float g_v[33554432];
__device__ float g_a[33554432];
__device__ float g_w[4194304];   // 4 pre-rounded weight matrices
__device__ int   g_idx[32768];   // compacted key indices per batch
__device__ int   g_cntb[256];    // per batch: #kept keys < (bi+1)*128, bi=0..7
__device__ float g_diag[32768];  // masked-diagonal fixup coefficient per (b,m)

// ---------------- helpers ----------------------------------------------------
__device__ __forceinline__ uint32_t cvt_tf32(float x) {
    uint32_t r;
    asm("cvt.rna.tf32.f32 %0, %1;" : "=r"(r) : "f"(x));
    return r;
}
__device__ __forceinline__ float round_tf32(float x) {
    return __uint_as_float(cvt_tf32(x));
}
__device__ __forceinline__ void cp_async16(uint32_t dst, const void* src) {
    asm volatile("cp.async.cg.shared.global [%0], [%1], 16;" :: "r"(dst), "l"(src));
}
__device__ __forceinline__ void cp_commit() {
    asm volatile("cp.async.commit_group;");
}

// swizzled smem index for K-major (NT) tiles (proven R2-R14)
__device__ __forceinline__ int idxA(int r, int k) {
    return r * BK + ((((k >> 2) ^ ((r >> 1) & 3)) << 2) | (k & 3));
}
// NN B tile stored [k][128] with quad ^= k&3
__device__ __forceinline__ int idxBnn(int k, int n) {
    return k * BN + ((((n >> 2) ^ (k & 3)) << 2) | (n & 3));
}

// ---------------- tf32 pre-rounding pass (all 4 weight matrices) -------------
__global__ void round_kernel(const float* __restrict__ s0, const float* __restrict__ s1,
                             const float* __restrict__ s2, const float* __restrict__ s3,
                             float* __restrict__ dst)
{
    int idx = blockIdx.x * blockDim.x + threadIdx.x;
    int wsel = idx >> 18;
    int off  = idx & 262143;
    const float* src = (wsel == 0) ? s0 : (wsel == 1) ? s1 : (wsel == 2) ? s2 : s3;
    float4 v = reinterpret_cast<const float4*>(src)[off];
    v.x = round_tf32(v.x); v.y = round_tf32(v.y);
    v.z = round_tf32(v.z); v.w = round_tf32(v.w);
    reinterpret_cast<float4*>(dst)[idx] = v;
}

// ---------------- gather: x = tf32(item_emb[positives] + pos_emb) ------------
__global__ void gather_kernel(const int* __restrict__ positives,
                              const float* __restrict__ item_emb,
                              const float* __restrict__ pos_emb,
                              float* __restrict__ x)
{
    int idx = blockIdx.x * blockDim.x + threadIdx.x;
    int row = idx >> 8;
    int c4  = idx & 255;
    int l   = row & 1023;
    int item = positives[row];
    float4 a = reinterpret_cast<const float4*>(item_emb)[(long long)item * 256 + c4];
    float4 p = reinterpret_cast<const float4*>(pos_emb)[l * 256 + c4];
    float4 o = make_float4(round_tf32(a.x + p.x), round_tf32(a.y + p.y),
                           round_tf32(a.z + p.z), round_tf32(a.w + p.w));
    reinterpret_cast<float4*>(x)[idx] = o;
}

// ---------------- mask compaction (one block per batch) ----------------------
__global__ void compact_kernel(const int* __restrict__ mask,
                               int* __restrict__ idx, int* __restrict__ cntb)
{
    __shared__ int sc[1024];
    int b = blockIdx.x, t = threadIdx.x;
    int mval = mask[b * 1024 + t];
    sc[t] = mval;
    __syncthreads();
    for (int off = 1; off < 1024; off <<= 1) {
        int add = (t >= off) ? sc[t - off] : 0;
        __syncthreads();
        sc[t] += add;
        __syncthreads();
    }
    int pos = sc[t];              // inclusive prefix count
    int total = sc[1023];
    if (mval) idx[b * 1024 + pos - 1] = t;
    if (t >= total) idx[b * 1024 + t] = 4096;   // sentinel
    if ((t & 127) == 127) cntb[b * 8 + (t >> 7)] = pos;
}

// ---------------- masked-diagonal coefficient (warp per row) ------------------
__global__ void diag_kernel(const float* __restrict__ q, const float* __restrict__ k,
                            const int* __restrict__ mask, const float* __restrict__ sw,
                            float* __restrict__ diag, float scale)
{
    int gw = blockIdx.x * 8 + (threadIdx.x >> 5);   // global row 0..32767
    int lane = threadIdx.x & 31;
    int m = gw & 1023;
    if (mask[gw]) { if (lane == 0) diag[gw] = 0.f; return; }
    const float* qr = q + (long long)gw * 1024;
    const float* kr = k + (long long)gw * 1024;
    float s = 0.f;
    #pragma unroll 8
    for (int i = lane; i < 1024; i += 32) s += qr[i] * kr[i];
    #pragma unroll
    for (int o = 16; o; o >>= 1) s += __shfl_xor_sync(0xFFFFFFFFu, s, o);
    if (lane == 0) {
        float t = fmaxf(s * sw[(long long)m * 1024 + m], 0.f);
        diag[gw] = round_tf32(t * t * scale);
    }
}

// ---------------- tf32 tensor-core GEMM (128x128 block, 4 warps of 64x64) ----
// EPI: 0 plain / AV-compacted (BNN), 1 silu->tf32, 2 col-scale->tf32,
//      3 compacted attention score->tf32
template<int EPI, bool BNN>
__global__ void __launch_bounds__(NTHREADS, 2)
gemm_kernel(const float* __restrict__ Ag, const float* __restrict__ Bg,
            float* __restrict__ Cg, int M, int N, int K,
            long long sA, long long sB, long long sC,
            const float* __restrict__ gamma, const float* __restrict__ beta,
            const float* __restrict__ sw, float scale,
            const int* __restrict__ idxv, const int* __restrict__ cntbv,
            const float* __restrict__ diagv)
{
    __shared__ uint32_t As[STAGES][BM * BK];   // 3 x 8 KB
    __shared__ uint32_t Bs[STAGES][BN * BK];   // 3 x 8 KB

    const int b = blockIdx.z;
    Ag += (long long)b * sA;
    Bg += (long long)b * sB;
    Cg += (long long)b * sC;
    const int* idxb = (EPI == 3 || BNN) ? (idxv + b * 1024) : idxv;

    const int tid  = threadIdx.x;
    const int lane = tid & 31;
    const int warp = tid >> 5;
    const int wm = (warp >> 1) * 64;
    const int wn = (warp & 1) * 64;
    const int m0 = blockIdx.y * BM;
    const int n0 = blockIdx.x * BN;
    const int tg = lane & 3;

    // Score: skip (zero-fill) blocks whose compacted columns are all > m0+127
    if (EPI == 3) {
        int lim = cntbv[b * 8 + blockIdx.y];
        if (n0 >= lim) {
            const float4 z4 = make_float4(0.f, 0.f, 0.f, 0.f);
            #pragma unroll
            for (int i = 0; i < (BM * BN / 4) / NTHREADS; i++) {
                int c = tid + i * NTHREADS;
                int r = c >> 5, qd = c & 31;
                *reinterpret_cast<float4*>(&Cg[(long long)(m0 + r) * N + n0 + qd * 4]) = z4;
            }
            return;
        }
    }

    float acc[4][8][4];
    #pragma unroll
    for (int i = 0; i < 4; i++)
        #pragma unroll
        for (int j = 0; j < 8; j++)
            #pragma unroll
            for (int c = 0; c < 4; c++) acc[i][j][c] = 0.f;

    int nK;
    if (BNN) nK = (cntbv[b * 8 + blockIdx.y] + BK - 1) / BK;   // compacted AV
    else     nK = K / BK;

    // NT B-operand source rows (gathered for score, identity otherwise)
    int growB[4];
    if (!BNN) {
        #pragma unroll
        for (int i = 0; i < 4; i++) {
            int r = (tid + i * NTHREADS) >> 2;
            growB[i] = (EPI == 3) ? (idxb[n0 + r] & 1023) : (n0 + r);
        }
    }

    auto loadStage = [&](int ks, int buf) {
        const int k0 = ks * BK;
        #pragma unroll
        for (int i = 0; i < 4; i++) {
            int c = tid + i * NTHREADS;
            int r = c >> 2, q = c & 3;
            const float* src = Ag + (long long)(m0 + r) * K + k0 + q * 4;
            int pq = q ^ ((r >> 1) & 3);
            cp_async16(__cvta_generic_to_shared(&As[buf][r * BK + pq * 4]), src);
        }
        if (BNN) {
            #pragma unroll
            for (int i = 0; i < 4; i++) {
                int c = tid + i * NTHREADS;
                int k = c >> 5, nq = c & 31;
                int vr = idxb[k0 + k] & 1023;               // gathered v row
                const float* src = Bg + (long long)vr * N + n0 + nq * 4;
                int pq = nq ^ (k & 3);
                cp_async16(__cvta_generic_to_shared(&Bs[buf][k * BN + pq * 4]), src);
            }
        } else {
            #pragma unroll
            for (int i = 0; i < 4; i++) {
                int c = tid + i * NTHREADS;
                int r = c >> 2, q = c & 3;
                const float* src = Bg + (long long)growB[i] * K + k0 + q * 4;
                int pq = q ^ ((r >> 1) & 3);
                cp_async16(__cvta_generic_to_shared(&Bs[buf][r * BK + pq * 4]), src);
            }
        }
        cp_commit();
    };

    if (nK > 0) {
        loadStage(0, 0);
        if (nK > 1) loadStage(1, 1);

        int buf = 0;
        for (int ks = 0; ks < nK; ks++) {
            if (ks + 2 < nK) {
                loadStage(ks + 2, (ks + 2) % STAGES);
                asm volatile("cp.async.wait_group 2;");
            } else if (ks + 1 < nK) {
                asm volatile("cp.async.wait_group 1;");
            } else {
                asm volatile("cp.async.wait_group 0;");
            }
            __syncthreads();

            const uint32_t* as = As[buf];
            const uint32_t* bs = Bs[buf];
            buf = (buf + 1 == STAGES) ? 0 : buf + 1;

            #pragma unroll
            for (int kk = 0; kk < BK; kk += 8) {
                const int kc = kk + tg;
                uint32_t af[4][4];
                #pragma unroll
                for (int mt = 0; mt < 4; mt++) {
                    int r = wm + mt * 16 + (lane >> 2);
                    af[mt][0] = as[idxA(r,     kc)];
                    af[mt][1] = as[idxA(r + 8, kc)];
                    af[mt][2] = as[idxA(r,     kc + 4)];
                    af[mt][3] = as[idxA(r + 8, kc + 4)];
                }
                uint32_t bf[8][2];
                #pragma unroll
                for (int nt = 0; nt < 8; nt++) {
                    int n = wn + nt * 8 + (lane >> 2);
                    if (BNN) {
                        bf[nt][0] = bs[idxBnn(kc,     n)];
                        bf[nt][1] = bs[idxBnn(kc + 4, n)];
                    } else {
                        bf[nt][0] = bs[idxA(n, kc)];
                        bf[nt][1] = bs[idxA(n, kc + 4)];
                    }
                }
                #pragma unroll
                for (int mt = 0; mt < 4; mt++)
                    #pragma unroll
                    for (int nt = 0; nt < 8; nt++) {
                        asm volatile(
                            "mma.sync.aligned.m16n8k8.row.col.f32.tf32.tf32.f32 "
                            "{%0,%1,%2,%3}, {%4,%5,%6,%7}, {%8,%9}, {%0,%1,%2,%3};"
                            : "+f"(acc[mt][nt][0]), "+f"(acc[mt][nt][1]),
                              "+f"(acc[mt][nt][2]), "+f"(acc[mt][nt][3])
                            : "r"(af[mt][0]), "r"(af[mt][1]), "r"(af[mt][2]), "r"(af[mt][3]),
                              "r"(bf[nt][0]), "r"(bf[nt][1]));
                    }
            }
            __syncthreads();
        }
    }

    // ---------------- epilogue ----------------
    #pragma unroll
    for (int mt = 0; mt < 4; mt++) {
        #pragma unroll
        for (int half = 0; half < 2; half++) {
            const int m = m0 + wm + mt * 16 + (lane >> 2) + half * 8;
            float dcoef = 0.f;
            if (BNN) dcoef = diagv[b * 1024 + m];
            #pragma unroll
            for (int nt = 0; nt < 8; nt++) {
                const int n = n0 + wn + nt * 8 + tg * 2;
                float v0 = acc[mt][nt][half * 2 + 0];
                float v1 = acc[mt][nt][half * 2 + 1];
                if (EPI == 1) {
                    v0 = round_tf32(v0 / (1.f + __expf(-v0)));
                    v1 = round_tf32(v1 / (1.f + __expf(-v1)));
                } else if (EPI == 2) {
                    v0 = round_tf32(v0 * gamma[n]     + beta[n]);
                    v1 = round_tf32(v1 * gamma[n + 1] + beta[n + 1]);
                } else if (EPI == 3) {
                    int ki0 = idxb[n];
                    int ki1 = idxb[n + 1];
                    bool keep0 = (ki0 <= m);
                    bool keep1 = (ki1 <= m);
                    float s0 = keep0 ? v0 * sw[(long long)m * 1024 + ki0] : 0.f;
                    float s1 = keep1 ? v1 * sw[(long long)m * 1024 + ki1] : 0.f;
                    s0 = fmaxf(s0, 0.f);
                    s1 = fmaxf(s1, 0.f);
                    v0 = round_tf32(s0 * s0 * scale);
                    v1 = round_tf32(s1 * s1 * scale);
                } else if (BNN) {   // AV: masked-diagonal fixup
                    float2 vv = *reinterpret_cast<const float2*>(&Bg[(long long)m * N + n]);
                    v0 += dcoef * vv.x;
                    v1 += dcoef * vv.y;
                }
                *reinterpret_cast<float2*>(&Cg[(long long)m * N + n]) = make_float2(v0, v1);
            }
        }
    }
}

// ---------------- launch ------------------------------------------------------
extern "C" void kernel_launch(void* const* d_in, const int* in_sizes, int n_in,
                              void* d_out, int out_size)
{
    const int*   positives = (const int*)  d_in[0];
    const int*   mask      = (const int*)  d_in[1];
    const float* item_emb  = (const float*)d_in[2];
    const float* pos_emb   = (const float*)d_in[3];
    const float* Wz        = (const float*)d_in[4];
    const float* Wv        = (const float*)d_in[5];
    const float* Wq        = (const float*)d_in[6];
    const float* Wk        = (const float*)d_in[7];
    const float* gq        = (const float*)d_in[8];
    const float* bq        = (const float*)d_in[9];
    const float* gk        = (const float*)d_in[10];
    const float* bk        = (const float*)d_in[11];
    const float* sw        = (const float*)d_in[12];
    float* out = (float*)d_out;

    float *x, *z, *q, *k, *v, *a, *w, *diagp;
    int *idxp, *cntbp;
    cudaGetSymbolAddress((void**)&x, g_x);
    cudaGetSymbolAddress((void**)&z, g_z);
    cudaGetSymbolAddress((void**)&q, g_q);
    cudaGetSymbolAddress((void**)&k, g_k);
    cudaGetSymbolAddress((void**)&v, g_v);
    cudaGetSymbolAddress((void**)&a, g_a);
    cudaGetSymbolAddress((void**)&w, g_w);
    cudaGetSymbolAddress((void**)&idxp,  g_idx);
    cudaGetSymbolAddress((void**)&cntbp, g_cntb);
    cudaGetSymbolAddress((void**)&diagp, g_diag);

    const int M = 32768, L = 1024;
    const long long SL = (long long)L * L;
    const float SC = 1.f / 1048576.f;
    float* wz = w;
    float* wv = w + 1048576;
    float* wq = w + 2097152;
    float* wk = w + 3145728;

    round_kernel<<<4096, 256>>>(Wz, Wv, Wq, Wk, w);
    gather_kernel<<<32768, 256>>>(positives, item_emb, pos_emb, x);
    compact_kernel<<<32, 1024>>>(mask, idxp, cntbp);

    dim3 gBig(L / BN, M / BM, 1);
    gemm_kernel<1, false><<<gBig, NTHREADS>>>(x, wz, z, M, L, L, 0, 0, 0,
        nullptr, nullptr, nullptr, 0.f, nullptr, nullptr, nullptr);
    gemm_kernel<1, false><<<gBig, NTHREADS>>>(x, wv, v, M, L, L, 0, 0, 0,
        nullptr, nullptr, nullptr, 0.f, nullptr, nullptr, nullptr);
    gemm_kernel<2, false><<<gBig, NTHREADS>>>(z, wq, q, M, L, L, 0, 0, 0,
        gq, bq, nullptr, 0.f, nullptr, nullptr, nullptr);
    gemm_kernel<2, false><<<gBig, NTHREADS>>>(z, wk, k, M, L, L, 0, 0, 0,
        gk, bk, nullptr, 0.f, nullptr, nullptr, nullptr);

    diag_kernel<<<4096, 256>>>(q, k, mask, sw, diagp, SC);

    dim3 gAtt(L / BN, L / BM, 32);
    // compacted score: a_c[m,j] over kept keys
    gemm_kernel<3, false><<<gAtt, NTHREADS>>>(q, k, a, L, L, L, SL, SL, SL,
        nullptr, nullptr, sw, SC, idxp, cntbp, nullptr);
    // compacted AV + masked-diagonal fixup
    gemm_kernel<0, true><<<gAtt, NTHREADS>>>(a, v, out, L, L, L, SL, SL, SL,
        nullptr, nullptr, nullptr, 0.f, idxp, cntbp, diagp);
}

// round 16
// speedup vs baseline: 1.0462x; 1.0462x over previous
#include <cuda_runtime.h>
#include <cstdint>

#define BM 128
#define BN 128
#define BK 16
#define NTHREADS 128
#define STAGES 3

// ---------------- scratch (device globals; no allocations allowed) ----------
__device__ float g_x[33554432];
__device__ float g_z[33554432];
__device__ float g_q[33554432];
__device__ float g_k[33554432];
__device__ float g_v[33554432];
__device__ float g_a[33554432];
__device__ float g_w[4194304];
__device__ int   g_idx[32768];   // compacted key indices per batch
__device__ int   g_cntb[256];    // per batch: #kept keys < (bi+1)*128
__device__ float g_diag[32768];  // masked-diagonal fixup coefficient

// ---------------- helpers ----------------------------------------------------
__device__ __forceinline__ uint32_t cvt_tf32(float x) {
    uint32_t r;
    asm("cvt.rna.tf32.f32 %0, %1;" : "=r"(r) : "f"(x));
    return r;
}
__device__ __forceinline__ float round_tf32(float x) {
    return __uint_as_float(cvt_tf32(x));
}
__device__ __forceinline__ void cp_async16(uint32_t dst, const void* src) {
    asm volatile("cp.async.cg.shared.global [%0], [%1], 16;" :: "r"(dst), "l"(src));
}
__device__ __forceinline__ void cp_commit() {
    asm volatile("cp.async.commit_group;");
}
__device__ __forceinline__ int idxA(int r, int k) {
    return r * BK + ((((k >> 2) ^ ((r >> 1) & 3)) << 2) | (k & 3));
}
__device__ __forceinline__ int idxBnn(int k, int n) {
    return k * BN + ((((n >> 2) ^ (k & 3)) << 2) | (n & 3));
}

#define MMA_TF32(acc, af, bf)                                             \
    asm volatile(                                                         \
        "mma.sync.aligned.m16n8k8.row.col.f32.tf32.tf32.f32 "             \
        "{%0,%1,%2,%3}, {%4,%5,%6,%7}, {%8,%9}, {%0,%1,%2,%3};"           \
        : "+f"((acc)[0]), "+f"((acc)[1]), "+f"((acc)[2]), "+f"((acc)[3])  \
        : "r"((af)[0]), "r"((af)[1]), "r"((af)[2]), "r"((af)[3]),         \
          "r"((bf)[0]), "r"((bf)[1]))

// ---------------- tf32 pre-rounding pass -------------------------------------
__global__ void round_kernel(const float* __restrict__ s0, const float* __restrict__ s1,
                             const float* __restrict__ s2, const float* __restrict__ s3,
                             float* __restrict__ dst)
{
    int idx = blockIdx.x * blockDim.x + threadIdx.x;
    int wsel = idx >> 18;
    int off  = idx & 262143;
    const float* src = (wsel == 0) ? s0 : (wsel == 1) ? s1 : (wsel == 2) ? s2 : s3;
    float4 v = reinterpret_cast<const float4*>(src)[off];
    v.x = round_tf32(v.x); v.y = round_tf32(v.y);
    v.z = round_tf32(v.z); v.w = round_tf32(v.w);
    reinterpret_cast<float4*>(dst)[idx] = v;
}

// ---------------- gather ------------------------------------------------------
__global__ void gather_kernel(const int* __restrict__ positives,
                              const float* __restrict__ item_emb,
                              const float* __restrict__ pos_emb,
                              float* __restrict__ x)
{
    int idx = blockIdx.x * blockDim.x + threadIdx.x;
    int row = idx >> 8;
    int c4  = idx & 255;
    int l   = row & 1023;
    int item = positives[row];
    float4 a = reinterpret_cast<const float4*>(item_emb)[(long long)item * 256 + c4];
    float4 p = reinterpret_cast<const float4*>(pos_emb)[l * 256 + c4];
    float4 o = make_float4(round_tf32(a.x + p.x), round_tf32(a.y + p.y),
                           round_tf32(a.z + p.z), round_tf32(a.w + p.w));
    reinterpret_cast<float4*>(x)[idx] = o;
}

// ---------------- mask compaction --------------------------------------------
__global__ void compact_kernel(const int* __restrict__ mask,
                               int* __restrict__ idx, int* __restrict__ cntb)
{
    __shared__ int sc[1024];
    int b = blockIdx.x, t = threadIdx.x;
    int mval = mask[b * 1024 + t];
    sc[t] = mval;
    __syncthreads();
    for (int off = 1; off < 1024; off <<= 1) {
        int add = (t >= off) ? sc[t - off] : 0;
        __syncthreads();
        sc[t] += add;
        __syncthreads();
    }
    int pos = sc[t];
    int total = sc[1023];
    if (mval) idx[b * 1024 + pos - 1] = t;
    if (t >= total) idx[b * 1024 + t] = 4096;
    if ((t & 127) == 127) cntb[b * 8 + (t >> 7)] = pos;
}

// ---------------- masked-diagonal coefficient ---------------------------------
__global__ void diag_kernel(const float* __restrict__ q, const float* __restrict__ k,
                            const int* __restrict__ mask, const float* __restrict__ sw,
                            float* __restrict__ diag, float scale)
{
    int gw = blockIdx.x * 8 + (threadIdx.x >> 5);
    int lane = threadIdx.x & 31;
    int m = gw & 1023;
    if (mask[gw]) { if (lane == 0) diag[gw] = 0.f; return; }
    const float* qr = q + (long long)gw * 1024;
    const float* kr = k + (long long)gw * 1024;
    float s = 0.f;
    #pragma unroll 8
    for (int i = lane; i < 1024; i += 32) s += qr[i] * kr[i];
    #pragma unroll
    for (int o = 16; o; o >>= 1) s += __shfl_xor_sync(0xFFFFFFFFu, s, o);
    if (lane == 0) {
        float t = fmaxf(s * sw[(long long)m * 1024 + m], 0.f);
        diag[gw] = round_tf32(t * t * scale);
    }
}

// =============================================================================
// DENSE GEMM — lean template, exactly the R14 mainloop (no batch, no indirection)
// C = A @ B^T, both K-major, M=32768, N=K=1024.  EPI: 1 silu, 2 gamma/beta.
// =============================================================================
template<int EPI>
__global__ void __launch_bounds__(NTHREADS, 2)
dense_gemm(const float* __restrict__ Ag, const float* __restrict__ Bg,
           float* __restrict__ Cg,
           const float* __restrict__ gamma, const float* __restrict__ beta)
{
    __shared__ uint32_t As[STAGES][BM * BK];
    __shared__ uint32_t Bs[STAGES][BN * BK];

    const int tid  = threadIdx.x;
    const int lane = tid & 31;
    const int warp = tid >> 5;
    const int wm = (warp >> 1) * 64;
    const int wn = (warp & 1) * 64;
    const int m0 = blockIdx.y * BM;
    const int n0 = blockIdx.x * BN;
    const int tg = lane & 3;
    const int N = 1024, K = 1024;

    float acc[4][8][4];
    #pragma unroll
    for (int i = 0; i < 4; i++)
        #pragma unroll
        for (int j = 0; j < 8; j++)
            #pragma unroll
            for (int c = 0; c < 4; c++) acc[i][j][c] = 0.f;

    const int nK = K / BK;

    auto loadStage = [&](int ks, int buf) {
        const int k0 = ks * BK;
        #pragma unroll
        for (int i = 0; i < 4; i++) {
            int c = tid + i * NTHREADS;
            int r = c >> 2, q = c & 3;
            int pq = q ^ ((r >> 1) & 3);
            cp_async16(__cvta_generic_to_shared(&As[buf][r * BK + pq * 4]),
                       Ag + (long long)(m0 + r) * K + k0 + q * 4);
            cp_async16(__cvta_generic_to_shared(&Bs[buf][r * BK + pq * 4]),
                       Bg + (long long)(n0 + r) * K + k0 + q * 4);
        }
        cp_commit();
    };

    loadStage(0, 0);
    loadStage(1, 1);

    int buf = 0;
    for (int ks = 0; ks < nK; ks++) {
        if (ks + 2 < nK) {
            loadStage(ks + 2, (ks + 2) % STAGES);
            asm volatile("cp.async.wait_group 2;");
        } else if (ks + 1 < nK) {
            asm volatile("cp.async.wait_group 1;");
        } else {
            asm volatile("cp.async.wait_group 0;");
        }
        __syncthreads();

        const uint32_t* as = As[buf];
        const uint32_t* bs = Bs[buf];
        buf = (buf + 1 == STAGES) ? 0 : buf + 1;

        #pragma unroll
        for (int kk = 0; kk < BK; kk += 8) {
            const int kc = kk + tg;
            uint32_t af[4][4];
            #pragma unroll
            for (int mt = 0; mt < 4; mt++) {
                int r = wm + mt * 16 + (lane >> 2);
                af[mt][0] = as[idxA(r,     kc)];
                af[mt][1] = as[idxA(r + 8, kc)];
                af[mt][2] = as[idxA(r,     kc + 4)];
                af[mt][3] = as[idxA(r + 8, kc + 4)];
            }
            uint32_t bf[8][2];
            #pragma unroll
            for (int nt = 0; nt < 8; nt++) {
                int n = wn + nt * 8 + (lane >> 2);
                bf[nt][0] = bs[idxA(n, kc)];
                bf[nt][1] = bs[idxA(n, kc + 4)];
            }
            #pragma unroll
            for (int mt = 0; mt < 4; mt++)
                #pragma unroll
                for (int nt = 0; nt < 8; nt++)
                    MMA_TF32(acc[mt][nt], af[mt], bf[nt]);
        }
        __syncthreads();
    }

    #pragma unroll
    for (int mt = 0; mt < 4; mt++) {
        #pragma unroll
        for (int half = 0; half < 2; half++) {
            const int m = m0 + wm + mt * 16 + (lane >> 2) + half * 8;
            #pragma unroll
            for (int nt = 0; nt < 8; nt++) {
                const int n = n0 + wn + nt * 8 + tg * 2;
                float v0 = acc[mt][nt][half * 2 + 0];
                float v1 = acc[mt][nt][half * 2 + 1];
                if (EPI == 1) {
                    v0 = round_tf32(v0 / (1.f + __expf(-v0)));
                    v1 = round_tf32(v1 / (1.f + __expf(-v1)));
                } else {
                    v0 = round_tf32(v0 * gamma[n]     + beta[n]);
                    v1 = round_tf32(v1 * gamma[n + 1] + beta[n + 1]);
                }
                *reinterpret_cast<float2*>(&Cg[(long long)m * N + n]) = make_float2(v0, v1);
            }
        }
    }
}

// =============================================================================
// COMPACTED SCORE GEMM — a_c[b, m, j] over kept keys (j compacted), NT.
// =============================================================================
__global__ void __launch_bounds__(NTHREADS, 2)
score_gemm(const float* __restrict__ q, const float* __restrict__ kmat,
           float* __restrict__ a, const float* __restrict__ sw,
           const int* __restrict__ idxv, const int* __restrict__ cntbv, float scale)
{
    __shared__ uint32_t As[STAGES][BM * BK];
    __shared__ uint32_t Bs[STAGES][BN * BK];

    const int b = blockIdx.z;
    const float* Ag = q    + (long long)b * 1048576;
    const float* Bg = kmat + (long long)b * 1048576;
    float*       Cg = a    + (long long)b * 1048576;
    const int* idxb = idxv + b * 1024;

    const int tid  = threadIdx.x;
    const int lane = tid & 31;
    const int warp = tid >> 5;
    const int wm = (warp >> 1) * 64;
    const int wn = (warp & 1) * 64;
    const int m0 = blockIdx.y * BM;
    const int n0 = blockIdx.x * BN;
    const int tg = lane & 3;
    const int N = 1024, K = 1024;

    const int lim = cntbv[b * 8 + blockIdx.y];
    if (n0 >= lim) {
        const float4 z4 = make_float4(0.f, 0.f, 0.f, 0.f);
        #pragma unroll
        for (int i = 0; i < (BM * BN / 4) / NTHREADS; i++) {
            int c = tid + i * NTHREADS;
            int r = c >> 5, qd = c & 31;
            *reinterpret_cast<float4*>(&Cg[(long long)(m0 + r) * N + n0 + qd * 4]) = z4;
        }
        return;
    }

    float acc[4][8][4];
    #pragma unroll
    for (int i = 0; i < 4; i++)
        #pragma unroll
        for (int j = 0; j < 8; j++)
            #pragma unroll
            for (int c = 0; c < 4; c++) acc[i][j][c] = 0.f;

    const int nK = K / BK;
    int growB[4];
    #pragma unroll
    for (int i = 0; i < 4; i++)
        growB[i] = idxb[n0 + ((tid + i * NTHREADS) >> 2)] & 1023;

    auto loadStage = [&](int ks, int buf) {
        const int k0 = ks * BK;
        #pragma unroll
        for (int i = 0; i < 4; i++) {
            int c = tid + i * NTHREADS;
            int r = c >> 2, qd = c & 3;
            int pq = qd ^ ((r >> 1) & 3);
            cp_async16(__cvta_generic_to_shared(&As[buf][r * BK + pq * 4]),
                       Ag + (long long)(m0 + r) * K + k0 + qd * 4);
            cp_async16(__cvta_generic_to_shared(&Bs[buf][r * BK + pq * 4]),
                       Bg + (long long)growB[i] * K + k0 + qd * 4);
        }
        cp_commit();
    };

    loadStage(0, 0);
    loadStage(1, 1);

    int buf = 0;
    for (int ks = 0; ks < nK; ks++) {
        if (ks + 2 < nK) {
            loadStage(ks + 2, (ks + 2) % STAGES);
            asm volatile("cp.async.wait_group 2;");
        } else if (ks + 1 < nK) {
            asm volatile("cp.async.wait_group 1;");
        } else {
            asm volatile("cp.async.wait_group 0;");
        }
        __syncthreads();

        const uint32_t* as = As[buf];
        const uint32_t* bs = Bs[buf];
        buf = (buf + 1 == STAGES) ? 0 : buf + 1;

        #pragma unroll
        for (int kk = 0; kk < BK; kk += 8) {
            const int kc = kk + tg;
            uint32_t af[4][4];
            #pragma unroll
            for (int mt = 0; mt < 4; mt++) {
                int r = wm + mt * 16 + (lane >> 2);
                af[mt][0] = as[idxA(r,     kc)];
                af[mt][1] = as[idxA(r + 8, kc)];
                af[mt][2] = as[idxA(r,     kc + 4)];
                af[mt][3] = as[idxA(r + 8, kc + 4)];
            }
            uint32_t bf[8][2];
            #pragma unroll
            for (int nt = 0; nt < 8; nt++) {
                int n = wn + nt * 8 + (lane >> 2);
                bf[nt][0] = bs[idxA(n, kc)];
                bf[nt][1] = bs[idxA(n, kc + 4)];
            }
            #pragma unroll
            for (int mt = 0; mt < 4; mt++)
                #pragma unroll
                for (int nt = 0; nt < 8; nt++)
                    MMA_TF32(acc[mt][nt], af[mt], bf[nt]);
        }
        __syncthreads();
    }

    #pragma unroll
    for (int mt = 0; mt < 4; mt++) {
        #pragma unroll
        for (int half = 0; half < 2; half++) {
            const int m = m0 + wm + mt * 16 + (lane >> 2) + half * 8;
            #pragma unroll
            for (int nt = 0; nt < 8; nt++) {
                const int n = n0 + wn + nt * 8 + tg * 2;
                float v0 = acc[mt][nt][half * 2 + 0];
                float v1 = acc[mt][nt][half * 2 + 1];
                int ki0 = idxb[n];
                int ki1 = idxb[n + 1];
                float s0 = (ki0 <= m) ? fmaxf(v0 * sw[(long long)m * 1024 + ki0], 0.f) : 0.f;
                float s1 = (ki1 <= m) ? fmaxf(v1 * sw[(long long)m * 1024 + ki1], 0.f) : 0.f;
                v0 = round_tf32(s0 * s0 * scale);
                v1 = round_tf32(s1 * s1 * scale);
                *reinterpret_cast<float2*>(&Cg[(long long)m * N + n]) = make_float2(v0, v1);
            }
        }
    }
}

// =============================================================================
// COMPACTED AV GEMM — out[b,m,d] = sum_j a_c[b,m,j] * v[b, idx[j], d] + diag·v[m]
// =============================================================================
__global__ void __launch_bounds__(NTHREADS, 2)
av_gemm(const float* __restrict__ a, const float* __restrict__ v,
        float* __restrict__ outp,
        const int* __restrict__ idxv, const int* __restrict__ cntbv,
        const float* __restrict__ diagv)
{
    __shared__ uint32_t As[STAGES][BM * BK];
    __shared__ uint32_t Bs[STAGES][BN * BK];

    const int b = blockIdx.z;
    const float* Ag = a  + (long long)b * 1048576;
    const float* Bg = v  + (long long)b * 1048576;
    float*       Cg = outp + (long long)b * 1048576;
    const int* idxb = idxv + b * 1024;

    const int tid  = threadIdx.x;
    const int lane = tid & 31;
    const int warp = tid >> 5;
    const int wm = (warp >> 1) * 64;
    const int wn = (warp & 1) * 64;
    const int m0 = blockIdx.y * BM;
    const int n0 = blockIdx.x * BN;
    const int tg = lane & 3;
    const int N = 1024, K = 1024;

    float acc[4][8][4];
    #pragma unroll
    for (int i = 0; i < 4; i++)
        #pragma unroll
        for (int j = 0; j < 8; j++)
            #pragma unroll
            for (int c = 0; c < 4; c++) acc[i][j][c] = 0.f;

    const int nK = (cntbv[b * 8 + blockIdx.y] + BK - 1) / BK;

    auto loadStage = [&](int ks, int buf) {
        const int k0 = ks * BK;
        #pragma unroll
        for (int i = 0; i < 4; i++) {
            int c = tid + i * NTHREADS;
            int r = c >> 2, qd = c & 3;
            int pq = qd ^ ((r >> 1) & 3);
            cp_async16(__cvta_generic_to_shared(&As[buf][r * BK + pq * 4]),
                       Ag + (long long)(m0 + r) * K + k0 + qd * 4);
        }
        #pragma unroll
        for (int i = 0; i < 4; i++) {
            int c = tid + i * NTHREADS;
            int kk = c >> 5, nq = c & 31;
            int vr = idxb[k0 + kk] & 1023;
            int pq = nq ^ (kk & 3);
            cp_async16(__cvta_generic_to_shared(&Bs[buf][kk * BN + pq * 4]),
                       Bg + (long long)vr * N + n0 + nq * 4);
        }
        cp_commit();
    };

    if (nK > 0) {
        loadStage(0, 0);
        if (nK > 1) loadStage(1, 1);

        int buf = 0;
        for (int ks = 0; ks < nK; ks++) {
            if (ks + 2 < nK) {
                loadStage(ks + 2, (ks + 2) % STAGES);
                asm volatile("cp.async.wait_group 2;");
            } else if (ks + 1 < nK) {
                asm volatile("cp.async.wait_group 1;");
            } else {
                asm volatile("cp.async.wait_group 0;");
            }
            __syncthreads();

            const uint32_t* as = As[buf];
            const uint32_t* bs = Bs[buf];
            buf = (buf + 1 == STAGES) ? 0 : buf + 1;

            #pragma unroll
            for (int kk = 0; kk < BK; kk += 8) {
                const int kc = kk + tg;
                uint32_t af[4][4];
                #pragma unroll
                for (int mt = 0; mt < 4; mt++) {
                    int r = wm + mt * 16 + (lane >> 2);
                    af[mt][0] = as[idxA(r,     kc)];
                    af[mt][1] = as[idxA(r + 8, kc)];
                    af[mt][2] = as[idxA(r,     kc + 4)];
                    af[mt][3] = as[idxA(r + 8, kc + 4)];
                }
                uint32_t bf[8][2];
                #pragma unroll
                for (int nt = 0; nt < 8; nt++) {
                    int n = wn + nt * 8 + (lane >> 2);
                    bf[nt][0] = bs[idxBnn(kc,     n)];
                    bf[nt][1] = bs[idxBnn(kc + 4, n)];
                }
                #pragma unroll
                for (int mt = 0; mt < 4; mt++)
                    #pragma unroll
                    for (int nt = 0; nt < 8; nt++)
                        MMA_TF32(acc[mt][nt], af[mt], bf[nt]);
            }
            __syncthreads();
        }
    }

    #pragma unroll
    for (int mt = 0; mt < 4; mt++) {
        #pragma unroll
        for (int half = 0; half < 2; half++) {
            const int m = m0 + wm + mt * 16 + (lane >> 2) + half * 8;
            const float dcoef = diagv[b * 1024 + m];
            #pragma unroll
            for (int nt = 0; nt < 8; nt++) {
                const int n = n0 + wn + nt * 8 + tg * 2;
                float2 vv = *reinterpret_cast<const float2*>(&Bg[(long long)m * N + n]);
                float v0 = acc[mt][nt][half * 2 + 0] + dcoef * vv.x;
                float v1 = acc[mt][nt][half * 2 + 1] + dcoef * vv.y;
                *reinterpret_cast<float2*>(&Cg[(long long)m * N + n]) = make_float2(v0, v1);
            }
        }
    }
}

// ---------------- launch ------------------------------------------------------
extern "C" void kernel_launch(void* const* d_in, const int* in_sizes, int n_in,
                              void* d_out, int out_size)
{
    const int*   positives = (const int*)  d_in[0];
    const int*   mask      = (const int*)  d_in[1];
    const float* item_emb  = (const float*)d_in[2];
    const float* pos_emb   = (const float*)d_in[3];
    const float* Wz        = (const float*)d_in[4];
    const float* Wv        = (const float*)d_in[5];
    const float* Wq        = (const float*)d_in[6];
    const float* Wk        = (const float*)d_in[7];
    const float* gq        = (const float*)d_in[8];
    const float* bq        = (const float*)d_in[9];
    const float* gk        = (const float*)d_in[10];
    const float* bk        = (const float*)d_in[11];
    const float* sw        = (const float*)d_in[12];
    float* out = (float*)d_out;

    float *x, *z, *q, *k, *v, *a, *w, *diagp;
    int *idxp, *cntbp;
    cudaGetSymbolAddress((void**)&x, g_x);
    cudaGetSymbolAddress((void**)&z, g_z);
    cudaGetSymbolAddress((void**)&q, g_q);
    cudaGetSymbolAddress((void**)&k, g_k);
    cudaGetSymbolAddress((void**)&v, g_v);
    cudaGetSymbolAddress((void**)&a, g_a);
    cudaGetSymbolAddress((void**)&w, g_w);
    cudaGetSymbolAddress((void**)&idxp,  g_idx);
    cudaGetSymbolAddress((void**)&cntbp, g_cntb);
    cudaGetSymbolAddress((void**)&diagp, g_diag);

    const int M = 32768, L = 1024;
    const float SC = 1.f / 1048576.f;
    float* wz = w;
    float* wv = w + 1048576;
    float* wq = w + 2097152;
    float* wk = w + 3145728;

    round_kernel<<<4096, 256>>>(Wz, Wv, Wq, Wk, w);
    gather_kernel<<<32768, 256>>>(positives, item_emb, pos_emb, x);
    compact_kernel<<<32, 1024>>>(mask, idxp, cntbp);

    dim3 gBig(L / BN, M / BM, 1);
    dense_gemm<1><<<gBig, NTHREADS>>>(x, wz, z, nullptr, nullptr);
    dense_gemm<1><<<gBig, NTHREADS>>>(x, wv, v, nullptr, nullptr);
    dense_gemm<2><<<gBig, NTHREADS>>>(z, wq, q, gq, bq);
    dense_gemm<2><<<gBig, NTHREADS>>>(z, wk, k, gk, bk);

    diag_kernel<<<4096, 256>>>(q, k, mask, sw, diagp, SC);

    dim3 gAtt(L / BN, L / BM, 32);
    score_gemm<<<gAtt, NTHREADS>>>(q, k, a, sw, idxp, cntbp, SC);
    av_gemm<<<gAtt, NTHREADS>>>(a, v, out, idxp, cntbp, diagp);
}

// round 17
// speedup vs baseline: 1.7801x; 1.7015x over previous
#include <cuda_runtime.h>
#include <cuda_fp16.h>
#include <cstdint>

#define BM 128
#define BN 128
#define BKH 32          // K halves per tile
#define BKW 16          // K b32 words per tile (2 halves per word)
#define NTHREADS 128
#define STAGES 3

// ---------------- scratch (device globals; no allocations allowed) ----------
__device__ __half g_xh[33554432];
__device__ __half g_zh[33554432];
__device__ __half g_qh[33554432];
__device__ __half g_kh[33554432];
__device__ __half g_vh[33554432];
__device__ __half g_ah[33554432];
__device__ __half g_vt[33554432];
__device__ __half g_wh[4194304];
__device__ int    g_idx[32768];
__device__ int    g_cntb[256];
__device__ float  g_diag[32768];

// scale plan (all powers of two, exact):
//   q,k stored *2^8  -> score acc = true*2^16, descale 2^-16
//   a stored  *2^56  -> av acc descale 2^-56
#define QK_SCALE 256.0f
#define SCORE_DESCALE 1.52587890625e-5f      // 2^-16
#define AV_DESCALE 1.3877787807814457e-17f   // 2^-56
#define SC (1.0f / 1048576.0f)               // 1/(L*D)

// ---------------- helpers ----------------------------------------------------
__device__ __forceinline__ void cp_async16(uint32_t dst, const void* src) {
    asm volatile("cp.async.cg.shared.global [%0], [%1], 16;" :: "r"(dst), "l"(src));
}
__device__ __forceinline__ void cp_commit() {
    asm volatile("cp.async.commit_group;");
}
// word-level swizzle, identical formula to the proven R14 layout (16 words/row)
__device__ __forceinline__ int idxA(int r, int w) {
    return r * BKW + ((((w >> 2) ^ ((r >> 1) & 3)) << 2) | (w & 3));
}

#define MMA_F16(acc, af, bf)                                              \
    asm volatile(                                                         \
        "mma.sync.aligned.m16n8k16.row.col.f32.f16.f16.f32 "              \
        "{%0,%1,%2,%3}, {%4,%5,%6,%7}, {%8,%9}, {%0,%1,%2,%3};"           \
        : "+f"((acc)[0]), "+f"((acc)[1]), "+f"((acc)[2]), "+f"((acc)[3])  \
        : "r"((af)[0]), "r"((af)[1]), "r"((af)[2]), "r"((af)[3]),         \
          "r"((bf)[0]), "r"((bf)[1]))

// ---------------- weight fp32 -> fp16 ----------------------------------------
__global__ void convert_w(const float* __restrict__ s0, const float* __restrict__ s1,
                          const float* __restrict__ s2, const float* __restrict__ s3,
                          __half* __restrict__ dst)
{
    int idx = blockIdx.x * blockDim.x + threadIdx.x;     // 1048576 float4s
    int wsel = idx >> 18;
    int off  = idx & 262143;
    const float* src = (wsel == 0) ? s0 : (wsel == 1) ? s1 : (wsel == 2) ? s2 : s3;
    float4 v = reinterpret_cast<const float4*>(src)[off];
    __half2* d = reinterpret_cast<__half2*>(dst) + idx * 2;
    d[0] = __floats2half2_rn(v.x, v.y);
    d[1] = __floats2half2_rn(v.z, v.w);
}

// ---------------- gather: x_h = fp16(item_emb[positives] + pos_emb) ----------
__global__ void gather_kernel(const int* __restrict__ positives,
                              const float* __restrict__ item_emb,
                              const float* __restrict__ pos_emb,
                              __half* __restrict__ x)
{
    int idx = blockIdx.x * blockDim.x + threadIdx.x;
    int row = idx >> 8;
    int c4  = idx & 255;
    int l   = row & 1023;
    int item = positives[row];
    float4 a = reinterpret_cast<const float4*>(item_emb)[(long long)item * 256 + c4];
    float4 p = reinterpret_cast<const float4*>(pos_emb)[l * 256 + c4];
    __half2* d = reinterpret_cast<__half2*>(x) + idx * 2;
    d[0] = __floats2half2_rn(a.x + p.x, a.y + p.y);
    d[1] = __floats2half2_rn(a.z + p.z, a.w + p.w);
}

// ---------------- mask compaction --------------------------------------------
__global__ void compact_kernel(const int* __restrict__ mask,
                               int* __restrict__ idx, int* __restrict__ cntb)
{
    __shared__ int sc[1024];
    int b = blockIdx.x, t = threadIdx.x;
    int mval = mask[b * 1024 + t];
    sc[t] = mval;
    __syncthreads();
    for (int off = 1; off < 1024; off <<= 1) {
        int add = (t >= off) ? sc[t - off] : 0;
        __syncthreads();
        sc[t] += add;
        __syncthreads();
    }
    int pos = sc[t];
    int total = sc[1023];
    if (mval) idx[b * 1024 + pos - 1] = t;
    if (t >= total) idx[b * 1024 + t] = 4096;
    if ((t & 127) == 127) cntb[b * 8 + (t >> 7)] = pos;
}

// ---------------- masked-diagonal coefficient (fp16 inputs) -------------------
__global__ void diag_kernel(const __half* __restrict__ q, const __half* __restrict__ k,
                            const int* __restrict__ mask, const float* __restrict__ sw,
                            float* __restrict__ diag)
{
    int gw = blockIdx.x * 8 + (threadIdx.x >> 5);
    int lane = threadIdx.x & 31;
    int m = gw & 1023;
    if (mask[gw]) { if (lane == 0) diag[gw] = 0.f; return; }
    const __half2* qr = reinterpret_cast<const __half2*>(q + (long long)gw * 1024);
    const __half2* kr = reinterpret_cast<const __half2*>(k + (long long)gw * 1024);
    float s = 0.f;
    #pragma unroll 4
    for (int i = lane; i < 512; i += 32) {
        float2 aa = __half22float2(qr[i]);
        float2 bb = __half22float2(kr[i]);
        s += aa.x * bb.x + aa.y * bb.y;
    }
    #pragma unroll
    for (int o = 16; o; o >>= 1) s += __shfl_xor_sync(0xFFFFFFFFu, s, o);
    if (lane == 0) {
        float t = fmaxf(s * SCORE_DESCALE * sw[(long long)m * 1024 + m], 0.f);
        diag[gw] = t * t * SC;
    }
}

// ---------------- gather-transpose: vt[b][d][j] = v[b][idx[j]][d] -------------
__global__ void vt_gather(const __half* __restrict__ v, __half* __restrict__ vt,
                          const int* __restrict__ idxv, const int* __restrict__ cntbv)
{
    int b = blockIdx.y;
    int t = blockIdx.x * 256 + threadIdx.x;   // 1048576 per batch
    int j = t & 1023;
    int d = t >> 10;
    int cnt = cntbv[b * 8 + 7];
    __half val = __float2half(0.f);
    if (j < cnt) {
        int r = idxv[b * 1024 + j];
        val = v[(long long)b * 1048576 + (long long)r * 1024 + d];
    }
    vt[(long long)b * 1048576 + (long long)d * 1024 + j] = val;
}

// =============================================================================
// DENSE fp16 GEMM: C = A @ B^T, K=1024 halves. EPI 1: silu; EPI 2: (g*x+b)*256.
// =============================================================================
template<int EPI>
__global__ void __launch_bounds__(NTHREADS, 2)
dense_gemm(const __half* __restrict__ Ag, const __half* __restrict__ Bg,
           __half* __restrict__ Cg,
           const float* __restrict__ gamma, const float* __restrict__ beta)
{
    __shared__ uint32_t As[STAGES][BM * BKW];
    __shared__ uint32_t Bs[STAGES][BN * BKW];

    const int tid  = threadIdx.x;
    const int lane = tid & 31;
    const int warp = tid >> 5;
    const int wm = (warp >> 1) * 64;
    const int wn = (warp & 1) * 64;
    const int m0 = blockIdx.y * BM;
    const int n0 = blockIdx.x * BN;
    const int tg = lane & 3;

    float acc[4][8][4];
    #pragma unroll
    for (int i = 0; i < 4; i++)
        #pragma unroll
        for (int j = 0; j < 8; j++)
            #pragma unroll
            for (int c = 0; c < 4; c++) acc[i][j][c] = 0.f;

    const int nK = 1024 / BKH;   // 32

    auto loadStage = [&](int ks, int buf) {
        const int k0 = ks * BKH;
        #pragma unroll
        for (int i = 0; i < 4; i++) {
            int c = tid + i * NTHREADS;
            int r = c >> 2, q = c & 3;
            int pw = (q ^ ((r >> 1) & 3)) << 2;
            cp_async16(__cvta_generic_to_shared(&As[buf][r * BKW + pw]),
                       Ag + (long long)(m0 + r) * 1024 + k0 + q * 8);
        }
        #pragma unroll
        for (int i = 0; i < 4; i++) {
            int c = tid + i * NTHREADS;
            int r = c >> 2, q = c & 3;
            int pw = (q ^ ((r >> 1) & 3)) << 2;
            cp_async16(__cvta_generic_to_shared(&Bs[buf][r * BKW + pw]),
                       Bg + (long long)(n0 + r) * 1024 + k0 + q * 8);
        }
        cp_commit();
    };

    loadStage(0, 0);
    loadStage(1, 1);

    int buf = 0;
    for (int ks = 0; ks < nK; ks++) {
        if (ks + 2 < nK) {
            loadStage(ks + 2, (ks + 2) % STAGES);
            asm volatile("cp.async.wait_group 2;");
        } else if (ks + 1 < nK) {
            asm volatile("cp.async.wait_group 1;");
        } else {
            asm volatile("cp.async.wait_group 0;");
        }
        __syncthreads();

        const uint32_t* as = As[buf];
        const uint32_t* bs = Bs[buf];
        buf = (buf + 1 == STAGES) ? 0 : buf + 1;

        #pragma unroll
        for (int kk = 0; kk < BKW; kk += 8) {
            const int kc = kk + tg;
            uint32_t af[4][4];
            #pragma unroll
            for (int mt = 0; mt < 4; mt++) {
                int r = wm + mt * 16 + (lane >> 2);
                af[mt][0] = as[idxA(r,     kc)];
                af[mt][1] = as[idxA(r + 8, kc)];
                af[mt][2] = as[idxA(r,     kc + 4)];
                af[mt][3] = as[idxA(r + 8, kc + 4)];
            }
            uint32_t bf[8][2];
            #pragma unroll
            for (int nt = 0; nt < 8; nt++) {
                int n = wn + nt * 8 + (lane >> 2);
                bf[nt][0] = bs[idxA(n, kc)];
                bf[nt][1] = bs[idxA(n, kc + 4)];
            }
            #pragma unroll
            for (int mt = 0; mt < 4; mt++)
                #pragma unroll
                for (int nt = 0; nt < 8; nt++)
                    MMA_F16(acc[mt][nt], af[mt], bf[nt]);
        }
        __syncthreads();
    }

    #pragma unroll
    for (int mt = 0; mt < 4; mt++) {
        #pragma unroll
        for (int half = 0; half < 2; half++) {
            const int m = m0 + wm + mt * 16 + (lane >> 2) + half * 8;
            #pragma unroll
            for (int nt = 0; nt < 8; nt++) {
                const int n = n0 + wn + nt * 8 + tg * 2;
                float v0 = acc[mt][nt][half * 2 + 0];
                float v1 = acc[mt][nt][half * 2 + 1];
                if (EPI == 1) {
                    v0 = v0 / (1.f + __expf(-v0));
                    v1 = v1 / (1.f + __expf(-v1));
                } else {
                    v0 = (v0 * gamma[n]     + beta[n])     * QK_SCALE;
                    v1 = (v1 * gamma[n + 1] + beta[n + 1]) * QK_SCALE;
                }
                *reinterpret_cast<__half2*>(&Cg[(long long)m * 1024 + n]) =
                    __floats2half2_rn(v0, v1);
            }
        }
    }
}

// =============================================================================
// COMPACTED SCORE fp16 GEMM: a'[b,m,j] = (relu(score*sw))^2 * 2^56 over kept keys
// =============================================================================
__global__ void __launch_bounds__(NTHREADS, 2)
score_gemm(const __half* __restrict__ q, const __half* __restrict__ kmat,
           __half* __restrict__ a, const float* __restrict__ sw,
           const int* __restrict__ idxv, const int* __restrict__ cntbv)
{
    __shared__ uint32_t As[STAGES][BM * BKW];
    __shared__ uint32_t Bs[STAGES][BN * BKW];

    const int b = blockIdx.z;
    const __half* Ag = q    + (long long)b * 1048576;
    const __half* Bg = kmat + (long long)b * 1048576;
    __half*       Cg = a    + (long long)b * 1048576;
    const int* idxb = idxv + b * 1024;

    const int tid  = threadIdx.x;
    const int lane = tid & 31;
    const int warp = tid >> 5;
    const int wm = (warp >> 1) * 64;
    const int wn = (warp & 1) * 64;
    const int m0 = blockIdx.y * BM;
    const int n0 = blockIdx.x * BN;
    const int tg = lane & 3;

    const int lim = cntbv[b * 8 + blockIdx.y];
    if (n0 >= lim) {
        const uint4 z4 = make_uint4(0, 0, 0, 0);
        #pragma unroll
        for (int i = 0; i < 16; i++) {
            int c = tid + i * NTHREADS;
            int r = c >> 4, qd = c & 15;          // 16 x 8-half chunks per row
            *reinterpret_cast<uint4*>(&Cg[(long long)(m0 + r) * 1024 + n0 + qd * 8]) = z4;
        }
        return;
    }

    float acc[4][8][4];
    #pragma unroll
    for (int i = 0; i < 4; i++)
        #pragma unroll
        for (int j = 0; j < 8; j++)
            #pragma unroll
            for (int c = 0; c < 4; c++) acc[i][j][c] = 0.f;

    const int nK = 1024 / BKH;
    int growB[4];
    #pragma unroll
    for (int i = 0; i < 4; i++)
        growB[i] = idxb[n0 + ((tid + i * NTHREADS) >> 2)] & 1023;

    auto loadStage = [&](int ks, int buf) {
        const int k0 = ks * BKH;
        #pragma unroll
        for (int i = 0; i < 4; i++) {
            int c = tid + i * NTHREADS;
            int r = c >> 2, qd = c & 3;
            int pw = (qd ^ ((r >> 1) & 3)) << 2;
            cp_async16(__cvta_generic_to_shared(&As[buf][r * BKW + pw]),
                       Ag + (long long)(m0 + r) * 1024 + k0 + qd * 8);
        }
        #pragma unroll
        for (int i = 0; i < 4; i++) {
            int c = tid + i * NTHREADS;
            int r = c >> 2, qd = c & 3;
            int pw = (qd ^ ((r >> 1) & 3)) << 2;
            cp_async16(__cvta_generic_to_shared(&Bs[buf][r * BKW + pw]),
                       Bg + (long long)growB[i] * 1024 + k0 + qd * 8);
        }
        cp_commit();
    };

    loadStage(0, 0);
    loadStage(1, 1);

    int buf = 0;
    for (int ks = 0; ks < nK; ks++) {
        if (ks + 2 < nK) {
            loadStage(ks + 2, (ks + 2) % STAGES);
            asm volatile("cp.async.wait_group 2;");
        } else if (ks + 1 < nK) {
            asm volatile("cp.async.wait_group 1;");
        } else {
            asm volatile("cp.async.wait_group 0;");
        }
        __syncthreads();

        const uint32_t* as = As[buf];
        const uint32_t* bs = Bs[buf];
        buf = (buf + 1 == STAGES) ? 0 : buf + 1;

        #pragma unroll
        for (int kk = 0; kk < BKW; kk += 8) {
            const int kc = kk + tg;
            uint32_t af[4][4];
            #pragma unroll
            for (int mt = 0; mt < 4; mt++) {
                int r = wm + mt * 16 + (lane >> 2);
                af[mt][0] = as[idxA(r,     kc)];
                af[mt][1] = as[idxA(r + 8, kc)];
                af[mt][2] = as[idxA(r,     kc + 4)];
                af[mt][3] = as[idxA(r + 8, kc + 4)];
            }
            uint32_t bf[8][2];
            #pragma unroll
            for (int nt = 0; nt < 8; nt++) {
                int n = wn + nt * 8 + (lane >> 2);
                bf[nt][0] = bs[idxA(n, kc)];
                bf[nt][1] = bs[idxA(n, kc + 4)];
            }
            #pragma unroll
            for (int mt = 0; mt < 4; mt++)
                #pragma unroll
                for (int nt = 0; nt < 8; nt++)
                    MMA_F16(acc[mt][nt], af[mt], bf[nt]);
        }
        __syncthreads();
    }

    // epilogue: true score s = acc*2^-16; u = relu(acc*sw) = s*sw*2^16;
    // stored a' = u^2*16 = (s*sw)^2 * 2^36 = a * 2^56   (a = (s*sw)^2 / 2^20)
    #pragma unroll
    for (int mt = 0; mt < 4; mt++) {
        #pragma unroll
        for (int half = 0; half < 2; half++) {
            const int m = m0 + wm + mt * 16 + (lane >> 2) + half * 8;
            #pragma unroll
            for (int nt = 0; nt < 8; nt++) {
                const int n = n0 + wn + nt * 8 + tg * 2;
                float v0 = acc[mt][nt][half * 2 + 0];
                float v1 = acc[mt][nt][half * 2 + 1];
                int ki0 = idxb[n];
                int ki1 = idxb[n + 1];
                float sw0 = sw[(long long)m * 1024 + (ki0 & 1023)];
                float sw1 = sw[(long long)m * 1024 + (ki1 & 1023)];
                float u0 = (ki0 <= m) ? fmaxf(v0 * sw0, 0.f) : 0.f;
                float u1 = (ki1 <= m) ? fmaxf(v1 * sw1, 0.f) : 0.f;
                *reinterpret_cast<__half2*>(&Cg[(long long)m * 1024 + n]) =
                    __floats2half2_rn(u0 * u0 * 16.f, u1 * u1 * 16.f);
            }
        }
    }
}

// =============================================================================
// COMPACTED AV fp16 GEMM: out = (a' @ vt^T)*2^-56 + diag*v[m]
// =============================================================================
__global__ void __launch_bounds__(NTHREADS, 2)
av_gemm(const __half* __restrict__ a, const __half* __restrict__ vt,
        const __half* __restrict__ v, float* __restrict__ outp,
        const int* __restrict__ cntbv, const float* __restrict__ diagv)
{
    __shared__ uint32_t As[STAGES][BM * BKW];
    __shared__ uint32_t Bs[STAGES][BN * BKW];

    const int b = blockIdx.z;
    const __half* Ag = a  + (long long)b * 1048576;
    const __half* Bg = vt + (long long)b * 1048576;
    const __half* Vg = v  + (long long)b * 1048576;
    float*        Cg = outp + (long long)b * 1048576;

    const int tid  = threadIdx.x;
    const int lane = tid & 31;
    const int warp = tid >> 5;
    const int wm = (warp >> 1) * 64;
    const int wn = (warp & 1) * 64;
    const int m0 = blockIdx.y * BM;
    const int n0 = blockIdx.x * BN;
    const int tg = lane & 3;

    float acc[4][8][4];
    #pragma unroll
    for (int i = 0; i < 4; i++)
        #pragma unroll
        for (int j = 0; j < 8; j++)
            #pragma unroll
            for (int c = 0; c < 4; c++) acc[i][j][c] = 0.f;

    const int nK = (cntbv[b * 8 + blockIdx.y] + BKH - 1) / BKH;

    auto loadStage = [&](int ks, int buf) {
        const int k0 = ks * BKH;
        #pragma unroll
        for (int i = 0; i < 4; i++) {
            int c = tid + i * NTHREADS;
            int r = c >> 2, qd = c & 3;
            int pw = (qd ^ ((r >> 1) & 3)) << 2;
            cp_async16(__cvta_generic_to_shared(&As[buf][r * BKW + pw]),
                       Ag + (long long)(m0 + r) * 1024 + k0 + qd * 8);
        }
        #pragma unroll
        for (int i = 0; i < 4; i++) {
            int c = tid + i * NTHREADS;
            int r = c >> 2, qd = c & 3;
            int pw = (qd ^ ((r >> 1) & 3)) << 2;
            cp_async16(__cvta_generic_to_shared(&Bs[buf][r * BKW + pw]),
                       Bg + (long long)(n0 + r) * 1024 + k0 + qd * 8);
        }
        cp_commit();
    };

    if (nK > 0) {
        loadStage(0, 0);
        if (nK > 1) loadStage(1, 1);

        int buf = 0;
        for (int ks = 0; ks < nK; ks++) {
            if (ks + 2 < nK) {
                loadStage(ks + 2, (ks + 2) % STAGES);
                asm volatile("cp.async.wait_group 2;");
            } else if (ks + 1 < nK) {
                asm volatile("cp.async.wait_group 1;");
            } else {
                asm volatile("cp.async.wait_group 0;");
            }
            __syncthreads();

            const uint32_t* as = As[buf];
            const uint32_t* bs = Bs[buf];
            buf = (buf + 1 == STAGES) ? 0 : buf + 1;

            #pragma unroll
            for (int kk = 0; kk < BKW; kk += 8) {
                const int kc = kk + tg;
                uint32_t af[4][4];
                #pragma unroll
                for (int mt = 0; mt < 4; mt++) {
                    int r = wm + mt * 16 + (lane >> 2);
                    af[mt][0] = as[idxA(r,     kc)];
                    af[mt][1] = as[idxA(r + 8, kc)];
                    af[mt][2] = as[idxA(r,     kc + 4)];
                    af[mt][3] = as[idxA(r + 8, kc + 4)];
                }
                uint32_t bf[8][2];
                #pragma unroll
                for (int nt = 0; nt < 8; nt++) {
                    int n = wn + nt * 8 + (lane >> 2);
                    bf[nt][0] = bs[idxA(n, kc)];
                    bf[nt][1] = bs[idxA(n, kc + 4)];
                }
                #pragma unroll
                for (int mt = 0; mt < 4; mt++)
                    #pragma unroll
                    for (int nt = 0; nt < 8; nt++)
                        MMA_F16(acc[mt][nt], af[mt], bf[nt]);
            }
            __syncthreads();
        }
    }

    #pragma unroll
    for (int mt = 0; mt < 4; mt++) {
        #pragma unroll
        for (int half = 0; half < 2; half++) {
            const int m = m0 + wm + mt * 16 + (lane >> 2) + half * 8;
            const float dcoef = diagv[b * 1024 + m];
            #pragma unroll
            for (int nt = 0; nt < 8; nt++) {
                const int n = n0 + wn + nt * 8 + tg * 2;
                float2 vv = __half22float2(
                    *reinterpret_cast<const __half2*>(&Vg[(long long)m * 1024 + n]));
                float o0 = acc[mt][nt][half * 2 + 0] * AV_DESCALE + dcoef * vv.x;
                float o1 = acc[mt][nt][half * 2 + 1] * AV_DESCALE + dcoef * vv.y;
                *reinterpret_cast<float2*>(&Cg[(long long)m * 1024 + n]) = make_float2(o0, o1);
            }
        }
    }
}

// ---------------- launch ------------------------------------------------------
extern "C" void kernel_launch(void* const* d_in, const int* in_sizes, int n_in,
                              void* d_out, int out_size)
{
    const int*   positives = (const int*)  d_in[0];
    const int*   mask      = (const int*)  d_in[1];
    const float* item_emb  = (const float*)d_in[2];
    const float* pos_emb   = (const float*)d_in[3];
    const float* Wz        = (const float*)d_in[4];
    const float* Wv        = (const float*)d_in[5];
    const float* Wq        = (const float*)d_in[6];
    const float* Wk        = (const float*)d_in[7];
    const float* gq        = (const float*)d_in[8];
    const float* bq        = (const float*)d_in[9];
    const float* gk        = (const float*)d_in[10];
    const float* bk        = (const float*)d_in[11];
    const float* sw        = (const float*)d_in[12];
    float* out = (float*)d_out;

    __half *xh, *zh, *qh, *kh, *vh, *ah, *vtp, *wh;
    float *diagp;
    int *idxp, *cntbp;
    cudaGetSymbolAddress((void**)&xh, g_xh);
    cudaGetSymbolAddress((void**)&zh, g_zh);
    cudaGetSymbolAddress((void**)&qh, g_qh);
    cudaGetSymbolAddress((void**)&kh, g_kh);
    cudaGetSymbolAddress((void**)&vh, g_vh);
    cudaGetSymbolAddress((void**)&ah, g_ah);
    cudaGetSymbolAddress((void**)&vtp, g_vt);
    cudaGetSymbolAddress((void**)&wh, g_wh);
    cudaGetSymbolAddress((void**)&idxp,  g_idx);
    cudaGetSymbolAddress((void**)&cntbp, g_cntb);
    cudaGetSymbolAddress((void**)&diagp, g_diag);

    __half* wzh = wh;
    __half* wvh = wh + 1048576;
    __half* wqh = wh + 2097152;
    __half* wkh = wh + 3145728;

    convert_w<<<4096, 256>>>(Wz, Wv, Wq, Wk, wh);
    gather_kernel<<<32768, 256>>>(positives, item_emb, pos_emb, xh);
    compact_kernel<<<32, 1024>>>(mask, idxp, cntbp);

    dim3 gBig(8, 256, 1);
    dense_gemm<1><<<gBig, NTHREADS>>>(xh, wzh, zh, nullptr, nullptr);
    dense_gemm<1><<<gBig, NTHREADS>>>(xh, wvh, vh, nullptr, nullptr);
    dense_gemm<2><<<gBig, NTHREADS>>>(zh, wqh, qh, gq, bq);
    dense_gemm<2><<<gBig, NTHREADS>>>(zh, wkh, kh, gk, bk);

    vt_gather<<<dim3(4096, 32), 256>>>(vh, vtp, idxp, cntbp);
    diag_kernel<<<4096, 256>>>(qh, kh, mask, sw, diagp);

    dim3 gAtt(8, 8, 32);
    score_gemm<<<gAtt, NTHREADS>>>(qh, kh, ah, sw, idxp, cntbp);
    av_gemm<<<gAtt, NTHREADS>>>(ah, vtp, vh, out, cntbp, diagp);
}